// round 6
// baseline (speedup 1.0000x reference)
#include <cuda_runtime.h>
#include <math.h>

#define B_ 8
#define C_ 256
#define T_ 2048
#define DEPTH_ 256
#define OCH 384
#define NCOL2 288
#define SSTR2 292

typedef unsigned long long u64t;

__device__ float g_Wt[C_*OCH];
__device__ float g_bf[OCH];
__device__ float g_v[B_*T_*256];      // [b][t][c] value proj
__device__ float g_qkT[B_*128*T_];    // [b][o][t], o<64: q*0.125, o>=64: k
__device__ float g_denom[T_];

static __device__ __forceinline__ u64t pk2(float a,float b){u64t r;asm("mov.b64 %0,{%1,%2};":"=l"(r):"f"(a),"f"(b));return r;}
static __device__ __forceinline__ u64t dup2(float a){return pk2(a,a);}
static __device__ __forceinline__ void fma2(u64t&d,u64t a,u64t b){asm("fma.rn.f32x2 %0,%1,%2,%3;":"=l"(d):"l"(a),"l"(b),"l"(d));}
static __device__ __forceinline__ void unpk(u64t v,float&x,float&y){asm("mov.b64 {%0,%1},%2;":"=f"(x),"=f"(y):"l"(v));}

__global__ void fold_k(
    const float* __restrict__ kW,const float* __restrict__ kb,const float* __restrict__ kg,
    const float* __restrict__ kbe,const float* __restrict__ kmu,const float* __restrict__ kva,
    const float* __restrict__ qW,const float* __restrict__ qb,const float* __restrict__ qg,
    const float* __restrict__ qbe,const float* __restrict__ qmu,const float* __restrict__ qva,
    const float* __restrict__ vW,const float* __restrict__ vb,const float* __restrict__ vg,
    const float* __restrict__ vbe,const float* __restrict__ vmu,const float* __restrict__ vva)
{
    int c = blockIdx.x, o = threadIdx.x;
    const float *W,*bb,*gg,*be,*mu,*va; int oo;
    if (o < 64)       { W=qW;bb=qb;gg=qg;be=qbe;mu=qmu;va=qva;oo=o; }
    else if (o < 128) { W=kW;bb=kb;gg=kg;be=kbe;mu=kmu;va=kva;oo=o-64; }
    else              { W=vW;bb=vb;gg=vg;be=vbe;mu=vmu;va=vva;oo=o-128; }
    float inv = gg[oo]*rsqrtf(va[oo]+1e-5f);
    g_Wt[c*OCH+o] = W[oo*C_+c]*inv;
    if (c == 0) g_bf[o] = (bb[oo]-mu[oo])*inv + be[oo];
}

// QKV projection 128x128 tile, FFMA2, writes q/k transposed, v row-major.
__global__ __launch_bounds__(256,3) void proj_k(const float* __restrict__ x)
{
    const int t0 = blockIdx.x*128, o0 = blockIdx.y*128, b = blockIdx.z;
    __shared__ float As[32*128], Bs[32*128];
    const int tid = threadIdx.x, mg = tid>>4, ng = tid&15;
    u64t acc[4][8];
    #pragma unroll
    for (int i = 0; i < 4; i++)
        #pragma unroll
        for (int j = 0; j < 8; j++) acc[i][j] = 0ull;

    for (int kc = 0; kc < C_; kc += 32) {
        __syncthreads();
        #pragma unroll
        for (int i = 0; i < 4; i++) {
            int f = tid + i*256, kk = f>>5, m4 = f&31;
            *(float4*)&As[kk*128+m4*4] = *(const float4*)&x[(b*C_+kc+kk)*T_+t0+m4*4];
            *(float4*)&Bs[kk*128+m4*4] = *(const float4*)&g_Wt[(kc+kk)*OCH+o0+m4*4];
        }
        __syncthreads();
        #pragma unroll 4
        for (int kk = 0; kk < 32; kk++) {
            ulonglong2 a01 = *(const ulonglong2*)&As[kk*128+mg*8];
            ulonglong2 a23 = *(const ulonglong2*)&As[kk*128+mg*8+4];
            float4 bA = *(const float4*)&Bs[kk*128+ng*8];
            float4 bB = *(const float4*)&Bs[kk*128+ng*8+4];
            u64t av[4] = {a01.x,a01.y,a23.x,a23.y};
            u64t bd[8] = {dup2(bA.x),dup2(bA.y),dup2(bA.z),dup2(bA.w),
                          dup2(bB.x),dup2(bB.y),dup2(bB.z),dup2(bB.w)};
            #pragma unroll
            for (int i = 0; i < 4; i++)
                #pragma unroll
                for (int j = 0; j < 8; j++) fma2(acc[i][j], av[i], bd[j]);
        }
    }
    float bias[8];
    #pragma unroll
    for (int j = 0; j < 8; j++) bias[j] = g_bf[o0+ng*8+j];

    if (o0 == 0) {   // q/k -> transposed [o][t], q pre-scaled by 0.125 (exact)
        #pragma unroll
        for (int j = 0; j < 8; j++) {
            int o = ng*8 + j;
            float sc = (o < 64) ? 0.125f : 1.f;
            float tv[8];
            #pragma unroll
            for (int i2 = 0; i2 < 4; i2++) {
                float lo,hi; unpk(acc[i2][j],lo,hi);
                tv[2*i2]   = fmaxf(lo+bias[j],0.f)*sc;
                tv[2*i2+1] = fmaxf(hi+bias[j],0.f)*sc;
            }
            float* dst = &g_qkT[((size_t)b*128+o)*T_ + t0 + mg*8];
            *(float4*)dst     = make_float4(tv[0],tv[1],tv[2],tv[3]);
            *(float4*)(dst+4) = make_float4(tv[4],tv[5],tv[6],tv[7]);
        }
    } else {         // v -> [t][256]
        const int vo = o0 - 128 + ng*8;
        #pragma unroll
        for (int i2 = 0; i2 < 4; i2++) {
            float lo[8],hi[8];
            #pragma unroll
            for (int j = 0; j < 8; j++) {
                unpk(acc[i2][j],lo[j],hi[j]);
                lo[j] = fmaxf(lo[j]+bias[j],0.f);
                hi[j] = fmaxf(hi[j]+bias[j],0.f);
            }
            int m = mg*8 + 2*i2;
            float* d0 = &g_v[((size_t)b*T_+t0+m)*256 + vo];
            *(float4*)d0       = make_float4(lo[0],lo[1],lo[2],lo[3]);
            *(float4*)(d0+4)   = make_float4(lo[4],lo[5],lo[6],lo[7]);
            *(float4*)(d0+256) = make_float4(hi[0],hi[1],hi[2],hi[3]);
            *(float4*)(d0+260) = make_float4(hi[4],hi[5],hi[6],hi[7]);
        }
    }
}

// Banded attention, 32-row tiles, 4 CTA/SM. j in [0,288), s = t0-256+j.
// Row r valid j in [max(r+1,256-t0), r+256]. Out-of-range reads are clamped
// (garbage values provably masked by the softmax window / P=0).
template<bool DENOM>
__global__ __launch_bounds__(256,4) void attn_k(const float* __restrict__ x,
                                                float* __restrict__ y)
{
    extern __shared__ float sm[];
    float* Ss = sm;               // [32][292] scores then P
    float* Qp = sm + 32*SSTR2;    // [64][32]
    float* Kt = Qp + 2048;        // [64][32]
    float* Vs = Qp;               // [16][256] alias (PV phase)

    const int t0 = blockIdx.x*32;
    const int b  = DENOM ? 0 : blockIdx.y;
    const int tid = threadIdx.x, warp = tid>>5, lane = tid&31;
    const int sbase = t0 - DEPTH_, jmin = DEPTH_ - t0;
    const int r0 = warp*4;
    const float* qT = &g_qkT[(size_t)b*128*T_];

    // stage Q [64 d][32 t]
    #pragma unroll
    for (int i = 0; i < 2; i++) {
        int f = tid + i*256, d = f>>3, c4 = f&7;
        *(float4*)&Qp[d*32+c4*4] = *(const float4*)&qT[d*T_ + t0 + c4*4];
    }

    // ---- QK scores, 9 chunks of 32 cols; warp = 4 rows x 32 cols ----
    for (int c0 = 0; c0 < NCOL2; c0 += 32) {
        if (c0 + 31 < jmin) continue;        // uniform skip, scores masked anyway
        __syncthreads();
        #pragma unroll
        for (int i = 0; i < 2; i++) {
            int f = tid + i*256, d = f>>3, c4 = f&7;
            int s = sbase + c0 + c4*4; if (s < 0) s = 0;   // clamp, garbage masked
            *(float4*)&Kt[d*32+c4*4] = *(const float4*)&qT[(64+d)*T_ + s];
        }
        __syncthreads();
        u64t a0 = 0ull, a1 = 0ull;
        #pragma unroll 8
        for (int d = 0; d < 64; d++) {
            ulonglong2 qq = *(const ulonglong2*)&Qp[d*32 + r0];   // uniform bcast
            u64t kk = dup2(Kt[d*32 + lane]);
            fma2(a0, qq.x, kk); fma2(a1, qq.y, kk);
        }
        float f0,f1,f2,f3; unpk(a0,f0,f1); unpk(a1,f2,f3);
        int c = c0 + lane;
        Ss[(r0+0)*SSTR2+c]=f0; Ss[(r0+1)*SSTR2+c]=f1;
        Ss[(r0+2)*SSTR2+c]=f2; Ss[(r0+3)*SSTR2+c]=f3;
    }
    __syncthreads();

    // ---- softmax (max floor 0 from masked entries, per reference) ----
    {
        int r = tid>>3, g = tid&7, t = t0+r;
        int jlo = max(r+1, jmin), jhi = r + DEPTH_;
        float mx = 0.f;
        for (int j = g; j < NCOL2; j += 8) {
            float v = Ss[r*SSTR2+j];
            if (j >= jlo && j <= jhi) mx = fmaxf(mx, v);
        }
        mx = fmaxf(mx, __shfl_xor_sync(0xffffffffu, mx, 1));
        mx = fmaxf(mx, __shfl_xor_sync(0xffffffffu, mx, 2));
        mx = fmaxf(mx, __shfl_xor_sync(0xffffffffu, mx, 4));
        if (DENOM) {
            float s = 0.f;
            for (int j = g; j < NCOL2; j += 8) {
                float v = Ss[r*SSTR2+j];
                if (j >= jlo && j <= jhi) s += __expf(v - mx);
            }
            s += __shfl_xor_sync(0xffffffffu, s, 1);
            s += __shfl_xor_sync(0xffffffffu, s, 2);
            s += __shfl_xor_sync(0xffffffffu, s, 4);
            if (g == 0) g_denom[t] = s + 1e-30f;
            return;
        }
        float invd = 1.f / g_denom[t];
        for (int j = g; j < NCOL2; j += 8) {
            float v = Ss[r*SSTR2+j];
            Ss[r*SSTR2+j] = (j >= jlo && j <= jhi) ? __expf(v-mx)*invd : 0.f;
        }
    }
    __syncthreads();

    // ---- P @ V: warp = 4 rows x 256 cols; lane cols {4l..4l+3, 4l+128..131} ----
    const int cL = lane*4;
    const int jloW = max(r0+1, jmin), jhiW = r0 + 3 + DEPTH_;
    u64t acc[4][4];
    #pragma unroll
    for (int i = 0; i < 4; i++)
        #pragma unroll
        for (int j = 0; j < 4; j++) acc[i][j] = 0ull;

    for (int ch = 0; ch < 18; ch++) {
        int c0 = ch*16;
        if (c0 + 15 < jmin) continue;        // uniform: P all zero here
        __syncthreads();
        #pragma unroll
        for (int i = 0; i < 4; i++) {
            int f = tid + i*256, row = f>>6, c4 = f&63;
            int s = sbase + c0 + row; if (s < 0) s = 0;   // P=0 masks garbage
            *(float4*)&Vs[row*256+c4*4] = *(const float4*)&g_v[((size_t)b*T_+s)*256 + c4*4];
        }
        __syncthreads();
        int jA = max(c0, jloW), jB = min(c0+15, jhiW);
        #pragma unroll 2
        for (int jj = jA; jj <= jB; jj++) {
            int lr = jj - c0;
            u64t p0 = dup2(Ss[(r0+0)*SSTR2+jj]);
            u64t p1 = dup2(Ss[(r0+1)*SSTR2+jj]);
            u64t p2 = dup2(Ss[(r0+2)*SSTR2+jj]);
            u64t p3 = dup2(Ss[(r0+3)*SSTR2+jj]);
            ulonglong2 va = *(const ulonglong2*)&Vs[lr*256 + cL];
            ulonglong2 vb = *(const ulonglong2*)&Vs[lr*256 + cL + 128];
            fma2(acc[0][0],p0,va.x); fma2(acc[0][1],p0,va.y); fma2(acc[0][2],p0,vb.x); fma2(acc[0][3],p0,vb.y);
            fma2(acc[1][0],p1,va.x); fma2(acc[1][1],p1,va.y); fma2(acc[1][2],p1,vb.x); fma2(acc[1][3],p1,vb.y);
            fma2(acc[2][0],p2,va.x); fma2(acc[2][1],p2,va.y); fma2(acc[2][2],p2,vb.x); fma2(acc[2][3],p2,vb.y);
            fma2(acc[3][0],p3,va.x); fma2(acc[3][1],p3,va.y); fma2(acc[3][2],p3,vb.x); fma2(acc[3][3],p3,vb.y);
        }
    }

    // ---- epilogue: 4 consecutive t per col -> direct float4 y = x + out ----
    float o_[4][8];
    #pragma unroll
    for (int i = 0; i < 4; i++) {
        unpk(acc[i][0], o_[i][0], o_[i][1]);
        unpk(acc[i][1], o_[i][2], o_[i][3]);
        unpk(acc[i][2], o_[i][4], o_[i][5]);
        unpk(acc[i][3], o_[i][6], o_[i][7]);
    }
    #pragma unroll
    for (int k = 0; k < 8; k++) {
        int c = (k < 4) ? (cL + k) : (cL + 124 + k);
        size_t gi = ((size_t)b*C_ + c)*T_ + t0 + r0;
        float4 xa = *(const float4*)&x[gi];
        float4 o4 = make_float4(xa.x + o_[0][k], xa.y + o_[1][k],
                                xa.z + o_[2][k], xa.w + o_[3][k]);
        *(float4*)&y[gi] = o4;
    }
}

extern "C" void kernel_launch(void* const* d_in, const int* in_sizes, int n_in,
                              void* d_out, int out_size)
{
    const float* x   = (const float*)d_in[0];
    const float* kW  = (const float*)d_in[1];
    const float* kb  = (const float*)d_in[2];
    const float* kg  = (const float*)d_in[3];
    const float* kbe = (const float*)d_in[4];
    const float* kmu = (const float*)d_in[5];
    const float* kva = (const float*)d_in[6];
    const float* qW  = (const float*)d_in[7];
    const float* qb  = (const float*)d_in[8];
    const float* qg  = (const float*)d_in[9];
    const float* qbe = (const float*)d_in[10];
    const float* qmu = (const float*)d_in[11];
    const float* qva = (const float*)d_in[12];
    const float* vW  = (const float*)d_in[13];
    const float* vb  = (const float*)d_in[14];
    const float* vg  = (const float*)d_in[15];
    const float* vbe = (const float*)d_in[16];
    const float* vmu = (const float*)d_in[17];
    const float* vva = (const float*)d_in[18];
    float* y = (float*)d_out;

    const int smem_attn = (32*SSTR2 + 4096) * sizeof(float);   // 53760 B
    cudaFuncSetAttribute(attn_k<true>,  cudaFuncAttributeMaxDynamicSharedMemorySize, smem_attn);
    cudaFuncSetAttribute(attn_k<false>, cudaFuncAttributeMaxDynamicSharedMemorySize, smem_attn);

    fold_k<<<C_, OCH>>>(kW,kb,kg,kbe,kmu,kva, qW,qb,qg,qbe,qmu,qva, vW,vb,vg,vbe,vmu,vva);
    proj_k<<<dim3(T_/128, 3, B_), 256>>>(x);
    attn_k<true><<<T_/32, 256, smem_attn>>>(x, y);
    attn_k<false><<<dim3(T_/32, B_), 256, smem_attn>>>(x, y);
}

// round 8
// speedup vs baseline: 1.2119x; 1.2119x over previous
#include <cuda_runtime.h>
#include <math.h>

#define B_ 8
#define C_ 256
#define T_ 2048
#define DEPTH_ 256
#define OCH 384
#define SSTR 321
#define SS_F (64*SSTR)          /* 20544 floats */
#define SM_F (SS_F + 8192)      /* 28736 floats = 114944 B */

typedef unsigned long long u64t;

__device__ float g_Wt[C_*OCH];
__device__ float g_bf[OCH];
__device__ float g_qkv[B_*T_*OCH];   // [b][t][384]: q|k|v
__device__ float g_qkT[B_*128*T_];   // [b][o][t]: o<64 q*0.125, o>=64 k
__device__ float g_denom[T_];

static __device__ __forceinline__ u64t pk2(float a,float b){u64t r;asm("mov.b64 %0,{%1,%2};":"=l"(r):"f"(a),"f"(b));return r;}
static __device__ __forceinline__ u64t dup2(float a){return pk2(a,a);}
static __device__ __forceinline__ void fma2(u64t&d,u64t a,u64t b){asm("fma.rn.f32x2 %0,%1,%2,%3;":"=l"(d):"l"(a),"l"(b),"l"(d));}
static __device__ __forceinline__ void unpk(u64t v,float&x,float&y){asm("mov.b64 {%0,%1},%2;":"=f"(x),"=f"(y):"l"(v));}
static __device__ __forceinline__ unsigned smem_u32(const void* p){
    unsigned a; asm("{ .reg .u64 t; cvta.to.shared.u64 t, %1; cvt.u32.u64 %0, t; }":"=r"(a):"l"(p)); return a;
}
static __device__ __forceinline__ void cpa16(unsigned dst, const void* src){
    asm volatile("cp.async.cg.shared.global [%0], [%1], 16;" :: "r"(dst), "l"(src));
}
#define CPCOMMIT asm volatile("cp.async.commit_group;" ::: "memory")
#define CPWAIT0  asm volatile("cp.async.wait_group 0;" ::: "memory")

// ---------------------------------------------------------------------------
__global__ void fold_k(
    const float* __restrict__ kW,const float* __restrict__ kb,const float* __restrict__ kg,
    const float* __restrict__ kbe,const float* __restrict__ kmu,const float* __restrict__ kva,
    const float* __restrict__ qW,const float* __restrict__ qb,const float* __restrict__ qg,
    const float* __restrict__ qbe,const float* __restrict__ qmu,const float* __restrict__ qva,
    const float* __restrict__ vW,const float* __restrict__ vb,const float* __restrict__ vg,
    const float* __restrict__ vbe,const float* __restrict__ vmu,const float* __restrict__ vva)
{
    int c = blockIdx.x, o = threadIdx.x;
    const float *W,*bb,*gg,*be,*mu,*va; int oo;
    if (o < 64)       { W=qW;bb=qb;gg=qg;be=qbe;mu=qmu;va=qva;oo=o; }
    else if (o < 128) { W=kW;bb=kb;gg=kg;be=kbe;mu=kmu;va=kva;oo=o-64; }
    else              { W=vW;bb=vb;gg=vg;be=vbe;mu=vmu;va=vva;oo=o-128; }
    float inv = gg[oo]*rsqrtf(va[oo]+1e-5f);
    g_Wt[c*OCH+o] = W[oo*C_+c]*inv;
    if (c == 0) g_bf[o] = (bb[oo]-mu[oo])*inv + be[oo];
}

// ---------------------------------------------------------------------------
// QKV projection: 128t x 64o tile, 256 thr, 8x4 per thread (acc 32 regs), FFMA2.
// grid (16, 6, 8). Writes g_qkv [t][384] coalesced.
// ---------------------------------------------------------------------------
__global__ __launch_bounds__(256,4) void proj_k(const float* __restrict__ x)
{
    const int t0 = blockIdx.x*128, o0 = blockIdx.y*64, b = blockIdx.z;
    __shared__ float As[32*128], Bs[32*64];
    const int tid = threadIdx.x, mg = tid>>4, ng = tid&15;
    u64t acc[4][4];
    #pragma unroll
    for (int i=0;i<4;i++){ acc[i][0]=0ull;acc[i][1]=0ull;acc[i][2]=0ull;acc[i][3]=0ull; }

    for (int kc = 0; kc < C_; kc += 32) {
        __syncthreads();
        #pragma unroll
        for (int i=0;i<4;i++){                       // As: 32x128 = 1024 float4
            int f = tid+i*256, kk = f>>5, m4 = f&31;
            *(float4*)&As[kk*128+m4*4] = *(const float4*)&x[((size_t)b*C_+kc+kk)*T_+t0+m4*4];
        }
        #pragma unroll
        for (int i=0;i<2;i++){                       // Bs: 32x64 = 512 float4
            int f = tid+i*256, kk = f>>4, n4 = f&15;
            *(float4*)&Bs[kk*64+n4*4] = *(const float4*)&g_Wt[(kc+kk)*OCH+o0+n4*4];
        }
        __syncthreads();
        #pragma unroll 4
        for (int kk=0;kk<32;kk++){
            float4 aA = *(const float4*)&As[kk*128+mg*8];
            float4 aB = *(const float4*)&As[kk*128+mg*8+4];
            ulonglong2 a0 = *(ulonglong2*)&aA, a1 = *(ulonglong2*)&aB;
            float4 bq = *(const float4*)&Bs[kk*64+ng*4];
            u64t b0=dup2(bq.x),b1=dup2(bq.y),b2=dup2(bq.z),b3=dup2(bq.w);
            u64t av[4] = {a0.x,a0.y,a1.x,a1.y};
            #pragma unroll
            for (int i=0;i<4;i++){
                fma2(acc[i][0],av[i],b0); fma2(acc[i][1],av[i],b1);
                fma2(acc[i][2],av[i],b2); fma2(acc[i][3],av[i],b3);
            }
        }
    }
    float bias[4];
    #pragma unroll
    for (int j=0;j<4;j++) bias[j] = g_bf[o0+ng*4+j];
    #pragma unroll
    for (int i=0;i<4;i++){
        float lo[4],hi[4];
        #pragma unroll
        for (int j=0;j<4;j++) unpk(acc[i][j],lo[j],hi[j]);
        int m = mg*8 + 2*i;
        float4 v;
        v.x=fmaxf(lo[0]+bias[0],0.f); v.y=fmaxf(lo[1]+bias[1],0.f);
        v.z=fmaxf(lo[2]+bias[2],0.f); v.w=fmaxf(lo[3]+bias[3],0.f);
        *(float4*)&g_qkv[((size_t)b*T_+t0+m)*OCH + o0 + ng*4] = v;
        v.x=fmaxf(hi[0]+bias[0],0.f); v.y=fmaxf(hi[1]+bias[1],0.f);
        v.z=fmaxf(hi[2]+bias[2],0.f); v.w=fmaxf(hi[3]+bias[3],0.f);
        *(float4*)&g_qkv[((size_t)b*T_+t0+m+1)*OCH + o0 + ng*4] = v;
    }
}

// ---------------------------------------------------------------------------
// Transpose q/k into [o][t] (q pre-scaled 0.125). grid (64,4,8), 256 thr.
// ---------------------------------------------------------------------------
__global__ __launch_bounds__(256) void trans_k()
{
    __shared__ float ts[32][33];
    const int t0 = blockIdx.x*32, o0 = blockIdx.y*32, b = blockIdx.z;
    {
        int ot = threadIdx.x & 31, tr = threadIdx.x >> 5;
        float sc = (o0 + ot < 64) ? 0.125f : 1.f;
        #pragma unroll
        for (int i=0;i<4;i++){
            int t = tr + i*8;
            ts[ot][t] = g_qkv[((size_t)b*T_ + t0 + t)*OCH + o0 + ot] * sc;
        }
    }
    __syncthreads();
    {
        int tt = threadIdx.x & 31, og = threadIdx.x >> 5;
        #pragma unroll
        for (int i=0;i<4;i++){
            int o = og + i*8;
            g_qkT[((size_t)b*128 + o0 + o)*T_ + t0 + tt] = ts[o][tt];
        }
    }
}

// ---------------------------------------------------------------------------
// Banded attention: 64-row tile, 512 thr, 2 CTA/SM, cp.async double-buffered.
// j in [0,320), s = t0-256+j. Row r valid j in [max(r+1,jmin), r+256].
// All staged s >= 0 by construction (chunks below jmin skipped, jmin 64-aligned).
// ---------------------------------------------------------------------------
template<bool DENOM>
__global__ __launch_bounds__(512,2) void attn_k(const float* __restrict__ x,
                                                float* __restrict__ y)
{
    extern __shared__ float sm[];
    float* Ss = sm;                 // [64][321]
    float* Qp = sm + SS_F;          // [64 d][64 t]
    float* Kt = sm + SS_F + 4096;   // 2 x [64 d][32 c]
    float* Vs = sm + SS_F;          // 2 x [16 s][256 c] (alias Qp+Kt)

    const int t0 = blockIdx.x*64;
    const int b  = DENOM ? 0 : blockIdx.y;
    const int tid = threadIdx.x, warp = tid>>5, lane = tid&31;
    const int r0 = warp*4;
    const int sbase = t0 - DEPTH_;
    const int jmin = (t0 < DEPTH_) ? DEPTH_ - t0 : 0;
    const float* qT = g_qkT + (size_t)b*128*T_;
    const unsigned qp_u = smem_u32(Qp), kt_u = smem_u32(Kt), vs_u = smem_u32(Vs);

    // stage Q [64 d][64 t] + first K chunk, one commit group
    #pragma unroll
    for (int i=0;i<2;i++){
        int u = tid + i*512, d = u>>4, c4 = u&15;
        cpa16(qp_u + (unsigned)(d*64 + c4*4)*4u, qT + (size_t)d*T_ + t0 + c4*4);
    }
    const int chs = jmin >> 5;
    {
        int d = tid>>3, c4 = tid&7;
        cpa16(kt_u + (unsigned)((chs&1)*2048 + d*32 + c4*4)*4u,
              qT + (size_t)(64+d)*T_ + sbase + chs*32 + c4*4);
    }
    CPCOMMIT;

    // ---- QK: chunks of 32 cols, double-buffered ----
    for (int ch = chs; ch < 10; ch++) {
        CPWAIT0; __syncthreads();
        if (ch + 1 < 10) {
            int d = tid>>3, c4 = tid&7;
            cpa16(kt_u + (unsigned)(((ch+1)&1)*2048 + d*32 + c4*4)*4u,
                  qT + (size_t)(64+d)*T_ + sbase + (ch+1)*32 + c4*4);
            CPCOMMIT;
        }
        const float* Kb = Kt + (ch&1)*2048;
        u64t a0 = 0ull, a1 = 0ull;
        #pragma unroll 8
        for (int d = 0; d < 64; d++) {
            float4 qf = *(const float4*)&Qp[d*64 + r0];     // warp-uniform bcast
            ulonglong2 qq = *(ulonglong2*)&qf;
            u64t kk = dup2(Kb[d*32 + lane]);
            fma2(a0, qq.x, kk); fma2(a1, qq.y, kk);
        }
        float f0,f1,f2,f3; unpk(a0,f0,f1); unpk(a1,f2,f3);
        int c = ch*32 + lane;
        Ss[(r0+0)*SSTR+c]=f0; Ss[(r0+1)*SSTR+c]=f1;
        Ss[(r0+2)*SSTR+c]=f2; Ss[(r0+3)*SSTR+c]=f3;
    }
    __syncthreads();                 // QK done; Qp/Kt region free for Vs

    const int ch16 = jmin >> 4;
    if (!DENOM) {                    // prefetch V chunk 0 (hidden under softmax)
        #pragma unroll
        for (int i=0;i<2;i++){
            int u = tid + i*512, row = u>>6, c4 = u&63;
            cpa16(vs_u + (unsigned)((ch16&1)*4096 + row*256 + c4*4)*4u,
                  &g_qkv[((size_t)b*T_ + sbase + ch16*16 + row)*OCH + 128 + c4*4]);
        }
        CPCOMMIT;
    }

    // ---- softmax (max floor 0 from masked entries; batch-0 denom, per ref) ----
    {
        int r = tid>>3, g = tid&7, t = t0 + r;
        int jlo = (r+1 > jmin) ? r+1 : jmin;
        int jhi = r + DEPTH_;
        float mx = 0.f;
        for (int j = jlo + g; j <= jhi; j += 8)
            mx = fmaxf(mx, Ss[r*SSTR + j]);
        mx = fmaxf(mx, __shfl_xor_sync(0xffffffffu, mx, 1));
        mx = fmaxf(mx, __shfl_xor_sync(0xffffffffu, mx, 2));
        mx = fmaxf(mx, __shfl_xor_sync(0xffffffffu, mx, 4));
        if (DENOM) {
            float s = 0.f;
            for (int j = jlo + g; j <= jhi; j += 8)
                s += __expf(Ss[r*SSTR + j] - mx);
            s += __shfl_xor_sync(0xffffffffu, s, 1);
            s += __shfl_xor_sync(0xffffffffu, s, 2);
            s += __shfl_xor_sync(0xffffffffu, s, 4);
            if (g == 0) g_denom[t] = s + 1e-30f;
            return;
        }
        float invd = 1.f / g_denom[t];
        for (int j = g; j < 320; j += 8) {
            float v = Ss[r*SSTR + j];
            Ss[r*SSTR + j] = (j >= jlo && j <= jhi) ? __expf(v - mx)*invd : 0.f;
        }
    }

    // ---- P @ V: warp = 4 rows x 256 cols; 16-row V chunks, double-buffered ----
    const int cL = lane*4;
    const int jAw = (r0+1 > jmin) ? r0+1 : jmin;
    const int jBw = r0 + 3 + DEPTH_;                 // <= 319
    u64t acc[4][4];
    #pragma unroll
    for (int i=0;i<4;i++){ acc[i][0]=0ull;acc[i][1]=0ull;acc[i][2]=0ull;acc[i][3]=0ull; }

    for (int ch = ch16; ch < 20; ch++) {
        CPWAIT0; __syncthreads();
        if (ch + 1 < 20) {
            #pragma unroll
            for (int i=0;i<2;i++){
                int u = tid + i*512, row = u>>6, c4 = u&63;
                cpa16(vs_u + (unsigned)(((ch+1)&1)*4096 + row*256 + c4*4)*4u,
                      &g_qkv[((size_t)b*T_ + sbase + (ch+1)*16 + row)*OCH + 128 + c4*4]);
            }
            CPCOMMIT;
        }
        const float* Vb = Vs + (ch&1)*4096;
        int c0 = ch*16;
        int jA = (c0 > jAw) ? c0 : jAw;
        int jB = (c0+15 < jBw) ? c0+15 : jBw;
        #pragma unroll 2
        for (int jj = jA; jj <= jB; jj++) {
            int lr = jj - c0;
            u64t p0 = dup2(Ss[(r0+0)*SSTR+jj]);      // warp-uniform bcasts
            u64t p1 = dup2(Ss[(r0+1)*SSTR+jj]);
            u64t p2 = dup2(Ss[(r0+2)*SSTR+jj]);
            u64t p3 = dup2(Ss[(r0+3)*SSTR+jj]);
            float4 va4 = *(const float4*)&Vb[lr*256 + cL];
            float4 vb4 = *(const float4*)&Vb[lr*256 + cL + 128];
            ulonglong2 va = *(ulonglong2*)&va4, vb = *(ulonglong2*)&vb4;
            fma2(acc[0][0],p0,va.x); fma2(acc[0][1],p0,va.y); fma2(acc[0][2],p0,vb.x); fma2(acc[0][3],p0,vb.y);
            fma2(acc[1][0],p1,va.x); fma2(acc[1][1],p1,va.y); fma2(acc[1][2],p1,vb.x); fma2(acc[1][3],p1,vb.y);
            fma2(acc[2][0],p2,va.x); fma2(acc[2][1],p2,va.y); fma2(acc[2][2],p2,vb.x); fma2(acc[2][3],p2,vb.y);
            fma2(acc[3][0],p3,va.x); fma2(acc[3][1],p3,va.y); fma2(acc[3][2],p3,vb.x); fma2(acc[3][3],p3,vb.y);
        }
    }

    // ---- epilogue: rows t0+r0..+3 consecutive -> direct float4 y = x + out ----
    float o_[4][8];
    #pragma unroll
    for (int i=0;i<4;i++){
        unpk(acc[i][0], o_[i][0], o_[i][1]);
        unpk(acc[i][1], o_[i][2], o_[i][3]);
        unpk(acc[i][2], o_[i][4], o_[i][5]);
        unpk(acc[i][3], o_[i][6], o_[i][7]);
    }
    #pragma unroll
    for (int k=0;k<8;k++){
        int c = (k < 4) ? (cL + k) : (cL + 124 + k);
        size_t gi = ((size_t)b*C_ + c)*T_ + t0 + r0;
        float4 xa = *(const float4*)&x[gi];
        float4 o4 = make_float4(xa.x + o_[0][k], xa.y + o_[1][k],
                                xa.z + o_[2][k], xa.w + o_[3][k]);
        *(float4*)&y[gi] = o4;
    }
}

// ---------------------------------------------------------------------------
extern "C" void kernel_launch(void* const* d_in, const int* in_sizes, int n_in,
                              void* d_out, int out_size)
{
    const float* x   = (const float*)d_in[0];
    const float* kW  = (const float*)d_in[1];
    const float* kb  = (const float*)d_in[2];
    const float* kg  = (const float*)d_in[3];
    const float* kbe = (const float*)d_in[4];
    const float* kmu = (const float*)d_in[5];
    const float* kva = (const float*)d_in[6];
    const float* qW  = (const float*)d_in[7];
    const float* qb  = (const float*)d_in[8];
    const float* qg  = (const float*)d_in[9];
    const float* qbe = (const float*)d_in[10];
    const float* qmu = (const float*)d_in[11];
    const float* qva = (const float*)d_in[12];
    const float* vW  = (const float*)d_in[13];
    const float* vb  = (const float*)d_in[14];
    const float* vg  = (const float*)d_in[15];
    const float* vbe = (const float*)d_in[16];
    const float* vmu = (const float*)d_in[17];
    const float* vva = (const float*)d_in[18];
    float* y = (float*)d_out;

    const int smem_attn = SM_F * sizeof(float);      // 114944 B
    cudaFuncSetAttribute(attn_k<true>,  cudaFuncAttributeMaxDynamicSharedMemorySize, smem_attn);
    cudaFuncSetAttribute(attn_k<false>, cudaFuncAttributeMaxDynamicSharedMemorySize, smem_attn);

    fold_k<<<C_, OCH>>>(kW,kb,kg,kbe,kmu,kva, qW,qb,qg,qbe,qmu,qva, vW,vb,vg,vbe,vmu,vva);
    proj_k<<<dim3(T_/128, OCH/64, B_), 256>>>(x);
    trans_k<<<dim3(T_/32, 4, B_), 256>>>();
    attn_k<true><<<T_/64, 512, smem_attn>>>(x, y);
    attn_k<false><<<dim3(T_/64, B_), 512, smem_attn>>>(x, y);
}

// round 9
// speedup vs baseline: 1.2507x; 1.0320x over previous
#include <cuda_runtime.h>
#include <math.h>

#define B_ 8
#define C_ 256
#define T_ 2048
#define DEPTH_ 256
#define OCH 384
#define SSTR 322
#define SS_F (64*SSTR)          /* 20608 floats */
#define SM_F (SS_F + 8192)      /* 28800 floats = 115200 B */

typedef unsigned long long u64t;

__device__ float g_Wt[C_*OCH];
__device__ float g_bf[OCH];
__device__ float g_qkv[B_*T_*OCH];   // [b][t][384]: q|k|v
__device__ float g_qkT[B_*128*T_];   // [b][o][t]: o<64 q*0.125, o>=64 k
__device__ float g_denom[T_];

static __device__ __forceinline__ u64t pk2(float a,float b){u64t r;asm("mov.b64 %0,{%1,%2};":"=l"(r):"f"(a),"f"(b));return r;}
static __device__ __forceinline__ u64t dup2(float a){return pk2(a,a);}
static __device__ __forceinline__ void fma2(u64t&d,u64t a,u64t b){asm("fma.rn.f32x2 %0,%1,%2,%3;":"=l"(d):"l"(a),"l"(b),"l"(d));}
static __device__ __forceinline__ void unpk(u64t v,float&x,float&y){asm("mov.b64 {%0,%1},%2;":"=f"(x),"=f"(y):"l"(v));}
static __device__ __forceinline__ unsigned smem_u32(const void* p){
    unsigned a; asm("{ .reg .u64 t; cvta.to.shared.u64 t, %1; cvt.u32.u64 %0, t; }":"=r"(a):"l"(p)); return a;
}
static __device__ __forceinline__ void cpa16(unsigned dst, const void* src){
    asm volatile("cp.async.cg.shared.global [%0], [%1], 16;" :: "r"(dst), "l"(src));
}
#define CPCOMMIT asm volatile("cp.async.commit_group;" ::: "memory")
#define CPWAIT0  asm volatile("cp.async.wait_group 0;" ::: "memory")

// ---------------------------------------------------------------------------
__global__ void fold_k(
    const float* __restrict__ kW,const float* __restrict__ kb,const float* __restrict__ kg,
    const float* __restrict__ kbe,const float* __restrict__ kmu,const float* __restrict__ kva,
    const float* __restrict__ qW,const float* __restrict__ qb,const float* __restrict__ qg,
    const float* __restrict__ qbe,const float* __restrict__ qmu,const float* __restrict__ qva,
    const float* __restrict__ vW,const float* __restrict__ vb,const float* __restrict__ vg,
    const float* __restrict__ vbe,const float* __restrict__ vmu,const float* __restrict__ vva)
{
    int c = blockIdx.x, o = threadIdx.x;
    const float *W,*bb,*gg,*be,*mu,*va; int oo;
    if (o < 64)       { W=qW;bb=qb;gg=qg;be=qbe;mu=qmu;va=qva;oo=o; }
    else if (o < 128) { W=kW;bb=kb;gg=kg;be=kbe;mu=kmu;va=kva;oo=o-64; }
    else              { W=vW;bb=vb;gg=vg;be=vbe;mu=vmu;va=vva;oo=o-128; }
    float inv = gg[oo]*rsqrtf(va[oo]+1e-5f);
    g_Wt[c*OCH+o] = W[oo*C_+c]*inv;
    if (c == 0) g_bf[o] = (bb[oo]-mu[oo])*inv + be[oo];
}

// ---------------------------------------------------------------------------
// QKV projection: 128t x 64o tile, 256 thr, 8x4 per thread, FFMA2.
// ---------------------------------------------------------------------------
__global__ __launch_bounds__(256,4) void proj_k(const float* __restrict__ x)
{
    const int t0 = blockIdx.x*128, o0 = blockIdx.y*64, b = blockIdx.z;
    __shared__ float As[32*128], Bs[32*64];
    const int tid = threadIdx.x, mg = tid>>4, ng = tid&15;
    u64t acc[4][4];
    #pragma unroll
    for (int i=0;i<4;i++){ acc[i][0]=0ull;acc[i][1]=0ull;acc[i][2]=0ull;acc[i][3]=0ull; }

    for (int kc = 0; kc < C_; kc += 32) {
        __syncthreads();
        #pragma unroll
        for (int i=0;i<4;i++){
            int f = tid+i*256, kk = f>>5, m4 = f&31;
            *(float4*)&As[kk*128+m4*4] = *(const float4*)&x[((size_t)b*C_+kc+kk)*T_+t0+m4*4];
        }
        #pragma unroll
        for (int i=0;i<2;i++){
            int f = tid+i*256, kk = f>>4, n4 = f&15;
            *(float4*)&Bs[kk*64+n4*4] = *(const float4*)&g_Wt[(kc+kk)*OCH+o0+n4*4];
        }
        __syncthreads();
        #pragma unroll 4
        for (int kk=0;kk<32;kk++){
            float4 aA = *(const float4*)&As[kk*128+mg*8];
            float4 aB = *(const float4*)&As[kk*128+mg*8+4];
            ulonglong2 a0 = *(ulonglong2*)&aA, a1 = *(ulonglong2*)&aB;
            float4 bq = *(const float4*)&Bs[kk*64+ng*4];
            u64t b0=dup2(bq.x),b1=dup2(bq.y),b2=dup2(bq.z),b3=dup2(bq.w);
            u64t av[4] = {a0.x,a0.y,a1.x,a1.y};
            #pragma unroll
            for (int i=0;i<4;i++){
                fma2(acc[i][0],av[i],b0); fma2(acc[i][1],av[i],b1);
                fma2(acc[i][2],av[i],b2); fma2(acc[i][3],av[i],b3);
            }
        }
    }
    float bias[4];
    #pragma unroll
    for (int j=0;j<4;j++) bias[j] = g_bf[o0+ng*4+j];
    #pragma unroll
    for (int i=0;i<4;i++){
        float lo[4],hi[4];
        #pragma unroll
        for (int j=0;j<4;j++) unpk(acc[i][j],lo[j],hi[j]);
        int m = mg*8 + 2*i;
        float4 v;
        v.x=fmaxf(lo[0]+bias[0],0.f); v.y=fmaxf(lo[1]+bias[1],0.f);
        v.z=fmaxf(lo[2]+bias[2],0.f); v.w=fmaxf(lo[3]+bias[3],0.f);
        *(float4*)&g_qkv[((size_t)b*T_+t0+m)*OCH + o0 + ng*4] = v;
        v.x=fmaxf(hi[0]+bias[0],0.f); v.y=fmaxf(hi[1]+bias[1],0.f);
        v.z=fmaxf(hi[2]+bias[2],0.f); v.w=fmaxf(hi[3]+bias[3],0.f);
        *(float4*)&g_qkv[((size_t)b*T_+t0+m+1)*OCH + o0 + ng*4] = v;
    }
}

// ---------------------------------------------------------------------------
// Transpose q/k into [o][t] (q pre-scaled 0.125). grid (64,4,8), 256 thr.
// ---------------------------------------------------------------------------
__global__ __launch_bounds__(256) void trans_k()
{
    __shared__ float ts[32][33];
    const int t0 = blockIdx.x*32, o0 = blockIdx.y*32, b = blockIdx.z;
    {
        int ot = threadIdx.x & 31, tr = threadIdx.x >> 5;
        float sc = (o0 + ot < 64) ? 0.125f : 1.f;
        #pragma unroll
        for (int i=0;i<4;i++){
            int t = tr + i*8;
            ts[ot][t] = g_qkv[((size_t)b*T_ + t0 + t)*OCH + o0 + ot] * sc;
        }
    }
    __syncthreads();
    {
        int tt = threadIdx.x & 31, og = threadIdx.x >> 5;
        #pragma unroll
        for (int i=0;i<4;i++){
            int o = og + i*8;
            g_qkT[((size_t)b*128 + o0 + o)*T_ + t0 + tt] = ts[o][tt];
        }
    }
}

// ---------------------------------------------------------------------------
// Denominator kernel: batch 0 only, 32-row tiles, grid 64, 256 thr.
// ---------------------------------------------------------------------------
__global__ __launch_bounds__(256) void denom_k()
{
    __shared__ float Ss[32*SSTR];
    __shared__ float Qp[64*32];
    __shared__ float Kt[2*64*32];
    const int t0 = blockIdx.x*32;
    const int tid = threadIdx.x, warp = tid>>5, lane = tid&31;
    const int r0 = warp*4;
    const int sbase = t0 - DEPTH_;
    const int jmin = (t0 < DEPTH_) ? DEPTH_ - t0 : 0;
    const float* qT = g_qkT;     // batch 0
    const unsigned qp_u = smem_u32(Qp), kt_u = smem_u32(Kt);

    #pragma unroll
    for (int i=0;i<2;i++){
        int f = tid + i*256, d = f>>3, c4 = f&7;
        cpa16(qp_u + (unsigned)(d*32 + c4*4)*4u, qT + (size_t)d*T_ + t0 + c4*4);
    }
    const int chs = jmin >> 5;
    #pragma unroll
    for (int i=0;i<2;i++){
        int f = tid + i*256, d = f>>3, c4 = f&7;
        cpa16(kt_u + (unsigned)((chs&1)*2048 + d*32 + c4*4)*4u,
              qT + (size_t)(64+d)*T_ + sbase + chs*32 + c4*4);
    }
    CPCOMMIT;

    for (int ch = chs; ch < 9; ch++) {          // rows<32 -> jhi<=287 -> 9 chunks
        CPWAIT0; __syncthreads();
        if (ch + 1 < 9) {
            #pragma unroll
            for (int i=0;i<2;i++){
                int f = tid + i*256, d = f>>3, c4 = f&7;
                cpa16(kt_u + (unsigned)(((ch+1)&1)*2048 + d*32 + c4*4)*4u,
                      qT + (size_t)(64+d)*T_ + sbase + (ch+1)*32 + c4*4);
            }
            CPCOMMIT;
        }
        const float* Kb = Kt + (ch&1)*2048;
        u64t a0 = 0ull, a1 = 0ull;
        #pragma unroll 8
        for (int d = 0; d < 64; d++) {
            float4 qf = *(const float4*)&Qp[d*32 + r0];
            ulonglong2 qq = *(ulonglong2*)&qf;
            u64t kk = dup2(Kb[d*32 + lane]);
            fma2(a0, qq.x, kk); fma2(a1, qq.y, kk);
        }
        float f0,f1,f2,f3; unpk(a0,f0,f1); unpk(a1,f2,f3);
        int c = ch*32 + lane;
        Ss[(r0+0)*SSTR+c]=f0; Ss[(r0+1)*SSTR+c]=f1;
        Ss[(r0+2)*SSTR+c]=f2; Ss[(r0+3)*SSTR+c]=f3;
    }
    __syncthreads();

    {
        int r = tid>>3, g = tid&7, t = t0 + r;
        int jlo = (r+1 > jmin) ? r+1 : jmin;
        int jhi = r + DEPTH_;
        float mx = 0.f;
        for (int j = jlo + g; j <= jhi; j += 8)
            mx = fmaxf(mx, Ss[r*SSTR + j]);
        mx = fmaxf(mx, __shfl_xor_sync(0xffffffffu, mx, 1));
        mx = fmaxf(mx, __shfl_xor_sync(0xffffffffu, mx, 2));
        mx = fmaxf(mx, __shfl_xor_sync(0xffffffffu, mx, 4));
        float s = 0.f;
        for (int j = jlo + g; j <= jhi; j += 8)
            s += __expf(Ss[r*SSTR + j] - mx);
        s += __shfl_xor_sync(0xffffffffu, s, 1);
        s += __shfl_xor_sync(0xffffffffu, s, 2);
        s += __shfl_xor_sync(0xffffffffu, s, 4);
        if (g == 0) g_denom[t] = s + 1e-30f;
    }
}

// ---------------------------------------------------------------------------
// Banded attention: 64-row tile, 512 thr, 2 CTA/SM, cp.async pipelined.
// PV mapping: warp = 8 rows x 128 cols (halves V crossbar traffic).
// ---------------------------------------------------------------------------
__global__ __launch_bounds__(512,2) void attn_k(const float* __restrict__ x,
                                                float* __restrict__ y)
{
    extern __shared__ float sm[];
    float* Ss = sm;                 // [64][322]
    float* Qp = sm + SS_F;          // [64 d][64 t]
    float* Kt = sm + SS_F + 4096;   // 2 x [64 d][32 c]
    float* Vs = sm + SS_F;          // 2 x [16 s][256 c] (alias Qp+Kt)

    const int t0 = blockIdx.x*64;
    const int b  = blockIdx.y;
    const int tid = threadIdx.x, warp = tid>>5, lane = tid&31;
    const int r0 = warp*4;
    const int sbase = t0 - DEPTH_;
    const int jmin = (t0 < DEPTH_) ? DEPTH_ - t0 : 0;
    const float* qT = g_qkT + (size_t)b*128*T_;
    const unsigned qp_u = smem_u32(Qp), kt_u = smem_u32(Kt), vs_u = smem_u32(Vs);

    // stage Q [64 d][64 t] + first K chunk
    #pragma unroll
    for (int i=0;i<2;i++){
        int u = tid + i*512, d = u>>4, c4 = u&15;
        cpa16(qp_u + (unsigned)(d*64 + c4*4)*4u, qT + (size_t)d*T_ + t0 + c4*4);
    }
    const int chs = jmin >> 5;
    {
        int d = tid>>3, c4 = tid&7;
        cpa16(kt_u + (unsigned)((chs&1)*2048 + d*32 + c4*4)*4u,
              qT + (size_t)(64+d)*T_ + sbase + chs*32 + c4*4);
    }
    CPCOMMIT;

    // ---- QK: chunks of 32 cols, double-buffered ----
    for (int ch = chs; ch < 10; ch++) {
        CPWAIT0; __syncthreads();
        if (ch + 1 < 10) {
            int d = tid>>3, c4 = tid&7;
            cpa16(kt_u + (unsigned)(((ch+1)&1)*2048 + d*32 + c4*4)*4u,
                  qT + (size_t)(64+d)*T_ + sbase + (ch+1)*32 + c4*4);
            CPCOMMIT;
        }
        const float* Kb = Kt + (ch&1)*2048;
        u64t a0 = 0ull, a1 = 0ull;
        #pragma unroll 8
        for (int d = 0; d < 64; d++) {
            float4 qf = *(const float4*)&Qp[d*64 + r0];
            ulonglong2 qq = *(ulonglong2*)&qf;
            u64t kk = dup2(Kb[d*32 + lane]);
            fma2(a0, qq.x, kk); fma2(a1, qq.y, kk);
        }
        float f0,f1,f2,f3; unpk(a0,f0,f1); unpk(a1,f2,f3);
        int c = ch*32 + lane;
        Ss[(r0+0)*SSTR+c]=f0; Ss[(r0+1)*SSTR+c]=f1;
        Ss[(r0+2)*SSTR+c]=f2; Ss[(r0+3)*SSTR+c]=f3;
    }
    __syncthreads();                 // QK done; Qp/Kt region free for Vs

    const int ch16 = jmin >> 4;
    {   // prefetch V chunk 0 (hidden under softmax)
        #pragma unroll
        for (int i=0;i<2;i++){
            int u = tid + i*512, row = u>>6, c4 = u&63;
            cpa16(vs_u + (unsigned)((ch16&1)*4096 + row*256 + c4*4)*4u,
                  &g_qkv[((size_t)b*T_ + sbase + ch16*16 + row)*OCH + 128 + c4*4]);
        }
        CPCOMMIT;
    }

    // ---- softmax: P = exp(s-max)/denom inside window, 0 outside ----
    {
        int r = tid>>3, g = tid&7, t = t0 + r;
        int jlo = (r+1 > jmin) ? r+1 : jmin;
        int jhi = r + DEPTH_;
        float mx = 0.f;
        for (int j = jlo + g; j <= jhi; j += 8)
            mx = fmaxf(mx, Ss[r*SSTR + j]);
        mx = fmaxf(mx, __shfl_xor_sync(0xffffffffu, mx, 1));
        mx = fmaxf(mx, __shfl_xor_sync(0xffffffffu, mx, 2));
        mx = fmaxf(mx, __shfl_xor_sync(0xffffffffu, mx, 4));
        float invd = 1.f / g_denom[t];
        for (int j = g; j < 320; j += 8) {
            float v = Ss[r*SSTR + j];
            Ss[r*SSTR + j] = (j >= jlo && j <= jhi) ? __expf(v - mx)*invd : 0.f;
        }
    }

    // ---- P @ V: warp = 8 rows x 128 cols; 16-row V chunks, double-buffered ----
    const int rg = warp >> 1, cg = warp & 1;
    const int r0p = rg * 8;
    const int cL = cg*128 + lane*4;
    const int jAw0 = (r0p+1 > jmin) ? r0p+1 : jmin;
    const int jAw = jAw0 & ~1;
    const int jBw = r0p + 7 + DEPTH_;            // <= 319
    u64t acc[8][2];
    #pragma unroll
    for (int i=0;i<8;i++){ acc[i][0]=0ull; acc[i][1]=0ull; }

    for (int ch = ch16; ch < 20; ch++) {
        CPWAIT0; __syncthreads();
        if (ch + 1 < 20) {
            #pragma unroll
            for (int i=0;i<2;i++){
                int u = tid + i*512, row = u>>6, c4 = u&63;
                cpa16(vs_u + (unsigned)(((ch+1)&1)*4096 + row*256 + c4*4)*4u,
                      &g_qkv[((size_t)b*T_ + sbase + (ch+1)*16 + row)*OCH + 128 + c4*4]);
            }
            CPCOMMIT;
        }
        const float* Vb = Vs + (ch&1)*4096;
        int c0 = ch*16;
        int bs = (c0 > jAw) ? c0 : jAw;          // even
        int be = (c0+14 < jBw) ? c0+14 : jBw;
        for (int j2 = bs; j2 <= be; j2 += 2) {
            float2 p2[8];
            #pragma unroll
            for (int i=0;i<8;i++)
                p2[i] = *(const float2*)&Ss[(r0p+i)*SSTR + j2];   // uniform bcast
            int lr = j2 - c0;
            {
                float4 vv = *(const float4*)&Vb[lr*256 + cL];
                ulonglong2 vp = *(ulonglong2*)&vv;
                #pragma unroll
                for (int i=0;i<8;i++){
                    u64t pd = dup2(p2[i].x);
                    fma2(acc[i][0], pd, vp.x); fma2(acc[i][1], pd, vp.y);
                }
            }
            {
                float4 vv = *(const float4*)&Vb[(lr+1)*256 + cL];
                ulonglong2 vp = *(ulonglong2*)&vv;
                #pragma unroll
                for (int i=0;i<8;i++){
                    u64t pd = dup2(p2[i].y);
                    fma2(acc[i][0], pd, vp.x); fma2(acc[i][1], pd, vp.y);
                }
            }
        }
    }

    // ---- epilogue: 8 consecutive t per col -> 2x float4 per col ----
    float o_[8][4];
    #pragma unroll
    for (int i=0;i<8;i++){
        unpk(acc[i][0], o_[i][0], o_[i][1]);
        unpk(acc[i][1], o_[i][2], o_[i][3]);
    }
    #pragma unroll
    for (int k=0;k<4;k++){
        size_t gi = ((size_t)b*C_ + cL + k)*T_ + t0 + r0p;
        float4 xa = *(const float4*)&x[gi];
        float4 o4 = make_float4(xa.x + o_[0][k], xa.y + o_[1][k],
                                xa.z + o_[2][k], xa.w + o_[3][k]);
        *(float4*)&y[gi] = o4;
        float4 xb = *(const float4*)&x[gi + 4];
        float4 o5 = make_float4(xb.x + o_[4][k], xb.y + o_[5][k],
                                xb.z + o_[6][k], xb.w + o_[7][k]);
        *(float4*)&y[gi + 4] = o5;
    }
}

// ---------------------------------------------------------------------------
extern "C" void kernel_launch(void* const* d_in, const int* in_sizes, int n_in,
                              void* d_out, int out_size)
{
    const float* x   = (const float*)d_in[0];
    const float* kW  = (const float*)d_in[1];
    const float* kb  = (const float*)d_in[2];
    const float* kg  = (const float*)d_in[3];
    const float* kbe = (const float*)d_in[4];
    const float* kmu = (const float*)d_in[5];
    const float* kva = (const float*)d_in[6];
    const float* qW  = (const float*)d_in[7];
    const float* qb  = (const float*)d_in[8];
    const float* qg  = (const float*)d_in[9];
    const float* qbe = (const float*)d_in[10];
    const float* qmu = (const float*)d_in[11];
    const float* qva = (const float*)d_in[12];
    const float* vW  = (const float*)d_in[13];
    const float* vb  = (const float*)d_in[14];
    const float* vg  = (const float*)d_in[15];
    const float* vbe = (const float*)d_in[16];
    const float* vmu = (const float*)d_in[17];
    const float* vva = (const float*)d_in[18];
    float* y = (float*)d_out;

    const int smem_attn = SM_F * sizeof(float);      // 115200 B
    cudaFuncSetAttribute(attn_k, cudaFuncAttributeMaxDynamicSharedMemorySize, smem_attn);

    fold_k<<<C_, OCH>>>(kW,kb,kg,kbe,kmu,kva, qW,qb,qg,qbe,qmu,qva, vW,vb,vg,vbe,vmu,vva);
    proj_k<<<dim3(T_/128, OCH/64, B_), 256>>>(x);
    trans_k<<<dim3(T_/32, 4, B_), 256>>>();
    denom_k<<<T_/32, 256>>>();
    attn_k<<<dim3(T_/64, B_), 512, smem_attn>>>(x, y);
}

// round 11
// speedup vs baseline: 1.3091x; 1.0468x over previous
#include <cuda_runtime.h>
#include <math.h>

#define B_ 8
#define C_ 256
#define T_ 2048
#define DEPTH_ 256
#define OCH 384
#define SSTR 322                /* even -> float2 row loads stay 8B aligned */
#define SS_F (64*SSTR)          /* 20608 floats */
#define AUX_F 6144              /* Qp 4096 + Kt 2048 ; Vs 4096 aliases */
#define SM_F (SS_F + AUX_F)     /* 26752 floats = 107008 B -> 2 CTA/SM */

typedef unsigned long long u64t;

__device__ float g_Wt[C_*OCH];
__device__ float g_bf[OCH];
__device__ float g_qkv[B_*T_*OCH];   // [b][t][384]: q|k|v
__device__ float g_qkT[B_*128*T_];   // [b][o][t]: o<64 q*0.125, o>=64 k
__device__ float g_denom[T_];

static __device__ __forceinline__ u64t pk2(float a,float b){u64t r;asm("mov.b64 %0,{%1,%2};":"=l"(r):"f"(a),"f"(b));return r;}
static __device__ __forceinline__ u64t dup2(float a){return pk2(a,a);}
static __device__ __forceinline__ void fma2(u64t&d,u64t a,u64t b){asm("fma.rn.f32x2 %0,%1,%2,%3;":"=l"(d):"l"(a),"l"(b),"l"(d));}
static __device__ __forceinline__ void unpk(u64t v,float&x,float&y){asm("mov.b64 {%0,%1},%2;":"=f"(x),"=f"(y):"l"(v));}
static __device__ __forceinline__ unsigned smem_u32(const void* p){
    unsigned a; asm("{ .reg .u64 t; cvta.to.shared.u64 t, %1; cvt.u32.u64 %0, t; }":"=r"(a):"l"(p)); return a;
}
static __device__ __forceinline__ void cpa16(unsigned dst, const void* src){
    asm volatile("cp.async.cg.shared.global [%0], [%1], 16;" :: "r"(dst), "l"(src));
}
#define CPCOMMIT asm volatile("cp.async.commit_group;" ::: "memory")
#define CPWAIT0  asm volatile("cp.async.wait_group 0;" ::: "memory")

// ---------------------------------------------------------------------------
__global__ void fold_k(
    const float* __restrict__ kW,const float* __restrict__ kb,const float* __restrict__ kg,
    const float* __restrict__ kbe,const float* __restrict__ kmu,const float* __restrict__ kva,
    const float* __restrict__ qW,const float* __restrict__ qb,const float* __restrict__ qg,
    const float* __restrict__ qbe,const float* __restrict__ qmu,const float* __restrict__ qva,
    const float* __restrict__ vW,const float* __restrict__ vb,const float* __restrict__ vg,
    const float* __restrict__ vbe,const float* __restrict__ vmu,const float* __restrict__ vva)
{
    int c = blockIdx.x, o = threadIdx.x;
    const float *W,*bb,*gg,*be,*mu,*va; int oo;
    if (o < 64)       { W=qW;bb=qb;gg=qg;be=qbe;mu=qmu;va=qva;oo=o; }
    else if (o < 128) { W=kW;bb=kb;gg=kg;be=kbe;mu=kmu;va=kva;oo=o-64; }
    else              { W=vW;bb=vb;gg=vg;be=vbe;mu=vmu;va=vva;oo=o-128; }
    float inv = gg[oo]*rsqrtf(va[oo]+1e-5f);
    g_Wt[c*OCH+o] = W[oo*C_+c]*inv;
    if (c == 0) g_bf[o] = (bb[oo]-mu[oo])*inv + be[oo];
}

// ---------------------------------------------------------------------------
// QKV projection: 128t x 64o tile, 256 thr, 8x4 per thread, FFMA2.
// ---------------------------------------------------------------------------
__global__ __launch_bounds__(256,4) void proj_k(const float* __restrict__ x)
{
    const int t0 = blockIdx.x*128, o0 = blockIdx.y*64, b = blockIdx.z;
    __shared__ float As[32*128], Bs[32*64];
    const int tid = threadIdx.x, mg = tid>>4, ng = tid&15;
    u64t acc[4][4];
    #pragma unroll
    for (int i=0;i<4;i++){ acc[i][0]=0ull;acc[i][1]=0ull;acc[i][2]=0ull;acc[i][3]=0ull; }

    for (int kc = 0; kc < C_; kc += 32) {
        __syncthreads();
        #pragma unroll
        for (int i=0;i<4;i++){
            int f = tid+i*256, kk = f>>5, m4 = f&31;
            *(float4*)&As[kk*128+m4*4] = *(const float4*)&x[((size_t)b*C_+kc+kk)*T_+t0+m4*4];
        }
        #pragma unroll
        for (int i=0;i<2;i++){
            int f = tid+i*256, kk = f>>4, n4 = f&15;
            *(float4*)&Bs[kk*64+n4*4] = *(const float4*)&g_Wt[(kc+kk)*OCH+o0+n4*4];
        }
        __syncthreads();
        #pragma unroll 4
        for (int kk=0;kk<32;kk++){
            float4 aA = *(const float4*)&As[kk*128+mg*8];
            float4 aB = *(const float4*)&As[kk*128+mg*8+4];
            ulonglong2 a0 = *(ulonglong2*)&aA, a1 = *(ulonglong2*)&aB;
            float4 bq = *(const float4*)&Bs[kk*64+ng*4];
            u64t b0=dup2(bq.x),b1=dup2(bq.y),b2=dup2(bq.z),b3=dup2(bq.w);
            u64t av[4] = {a0.x,a0.y,a1.x,a1.y};
            #pragma unroll
            for (int i=0;i<4;i++){
                fma2(acc[i][0],av[i],b0); fma2(acc[i][1],av[i],b1);
                fma2(acc[i][2],av[i],b2); fma2(acc[i][3],av[i],b3);
            }
        }
    }
    float bias[4];
    #pragma unroll
    for (int j=0;j<4;j++) bias[j] = g_bf[o0+ng*4+j];
    #pragma unroll
    for (int i=0;i<4;i++){
        float lo[4],hi[4];
        #pragma unroll
        for (int j=0;j<4;j++) unpk(acc[i][j],lo[j],hi[j]);
        int m = mg*8 + 2*i;
        float4 v;
        v.x=fmaxf(lo[0]+bias[0],0.f); v.y=fmaxf(lo[1]+bias[1],0.f);
        v.z=fmaxf(lo[2]+bias[2],0.f); v.w=fmaxf(lo[3]+bias[3],0.f);
        *(float4*)&g_qkv[((size_t)b*T_+t0+m)*OCH + o0 + ng*4] = v;
        v.x=fmaxf(hi[0]+bias[0],0.f); v.y=fmaxf(hi[1]+bias[1],0.f);
        v.z=fmaxf(hi[2]+bias[2],0.f); v.w=fmaxf(hi[3]+bias[3],0.f);
        *(float4*)&g_qkv[((size_t)b*T_+t0+m+1)*OCH + o0 + ng*4] = v;
    }
}

// ---------------------------------------------------------------------------
// Transpose q/k into [o][t] (q pre-scaled 0.125). grid (64,4,8), 256 thr.
// ---------------------------------------------------------------------------
__global__ __launch_bounds__(256) void trans_k()
{
    __shared__ float ts[32][33];
    const int t0 = blockIdx.x*32, o0 = blockIdx.y*32, b = blockIdx.z;
    {
        int ot = threadIdx.x & 31, tr = threadIdx.x >> 5;
        float sc = (o0 + ot < 64) ? 0.125f : 1.f;
        #pragma unroll
        for (int i=0;i<4;i++){
            int t = tr + i*8;
            ts[ot][t] = g_qkv[((size_t)b*T_ + t0 + t)*OCH + o0 + ot] * sc;
        }
    }
    __syncthreads();
    {
        int tt = threadIdx.x & 31, og = threadIdx.x >> 5;
        #pragma unroll
        for (int i=0;i<4;i++){
            int o = og + i*8;
            g_qkT[((size_t)b*128 + o0 + o)*T_ + t0 + tt] = ts[o][tt];
        }
    }
}

// ---------------------------------------------------------------------------
// Denominator kernel: batch 0 only, 32-row tiles, grid 64, 256 thr.
// ---------------------------------------------------------------------------
__global__ __launch_bounds__(256) void denom_k()
{
    __shared__ float Ss[32*SSTR];
    __shared__ float Qp[64*32];
    __shared__ float Kt[2*64*32];
    const int t0 = blockIdx.x*32;
    const int tid = threadIdx.x, warp = tid>>5, lane = tid&31;
    const int r0 = warp*4;
    const int sbase = t0 - DEPTH_;
    const int jmin = (t0 < DEPTH_) ? DEPTH_ - t0 : 0;
    const float* qT = g_qkT;     // batch 0
    const unsigned qp_u = smem_u32(Qp), kt_u = smem_u32(Kt);

    #pragma unroll
    for (int i=0;i<2;i++){
        int f = tid + i*256, d = f>>3, c4 = f&7;
        cpa16(qp_u + (unsigned)(d*32 + c4*4)*4u, qT + (size_t)d*T_ + t0 + c4*4);
    }
    const int chs = jmin >> 5;
    #pragma unroll
    for (int i=0;i<2;i++){
        int f = tid + i*256, d = f>>3, c4 = f&7;
        cpa16(kt_u + (unsigned)((chs&1)*2048 + d*32 + c4*4)*4u,
              qT + (size_t)(64+d)*T_ + sbase + chs*32 + c4*4);
    }
    CPCOMMIT;

    for (int ch = chs; ch < 9; ch++) {
        CPWAIT0; __syncthreads();
        if (ch + 1 < 9) {
            #pragma unroll
            for (int i=0;i<2;i++){
                int f = tid + i*256, d = f>>3, c4 = f&7;
                cpa16(kt_u + (unsigned)(((ch+1)&1)*2048 + d*32 + c4*4)*4u,
                      qT + (size_t)(64+d)*T_ + sbase + (ch+1)*32 + c4*4);
            }
            CPCOMMIT;
        }
        const float* Kb = Kt + (ch&1)*2048;
        u64t a0 = 0ull, a1 = 0ull;
        #pragma unroll 8
        for (int d = 0; d < 64; d++) {
            float4 qf = *(const float4*)&Qp[d*32 + r0];
            ulonglong2 qq = *(ulonglong2*)&qf;
            u64t kk = dup2(Kb[d*32 + lane]);
            fma2(a0, qq.x, kk); fma2(a1, qq.y, kk);
        }
        float f0,f1,f2,f3; unpk(a0,f0,f1); unpk(a1,f2,f3);
        int c = ch*32 + lane;
        Ss[(r0+0)*SSTR+c]=f0; Ss[(r0+1)*SSTR+c]=f1;
        Ss[(r0+2)*SSTR+c]=f2; Ss[(r0+3)*SSTR+c]=f3;
    }
    __syncthreads();

    {
        int r = tid>>3, g = tid&7, t = t0 + r;
        int jlo = (r+1 > jmin) ? r+1 : jmin;
        int jhi = r + DEPTH_;
        float mx = 0.f;
        for (int j = jlo + g; j <= jhi; j += 8)
            mx = fmaxf(mx, Ss[r*SSTR + j]);
        mx = fmaxf(mx, __shfl_xor_sync(0xffffffffu, mx, 1));
        mx = fmaxf(mx, __shfl_xor_sync(0xffffffffu, mx, 2));
        mx = fmaxf(mx, __shfl_xor_sync(0xffffffffu, mx, 4));
        float s = 0.f;
        for (int j = jlo + g; j <= jhi; j += 8)
            s += __expf(Ss[r*SSTR + j] - mx);
        s += __shfl_xor_sync(0xffffffffu, s, 1);
        s += __shfl_xor_sync(0xffffffffu, s, 2);
        s += __shfl_xor_sync(0xffffffffu, s, 4);
        if (g == 0) g_denom[t] = s + 1e-30f;
    }
}

// ---------------------------------------------------------------------------
// Banded attention: 64-row tile, 512 thr, TRUE 2 CTA/SM (107KB smem).
// Single-buffered K/V chunks with register prefetch (LDG next chunk during
// compute of current). PV mapping: warp = 8 rows x 128 cols.
// ---------------------------------------------------------------------------
__global__ __launch_bounds__(512,2) void attn_k(const float* __restrict__ x,
                                                float* __restrict__ y)
{
    extern __shared__ float sm[];
    float* Ss = sm;                 // [64][322]
    float* Qp = sm + SS_F;          // [64 d][64 t]
    float* Kt = Qp + 4096;          // [64 d][32 c] single buffer
    float* Vs = sm + SS_F;          // [16 s][256 c] single buffer (alias Qp)

    const int t0 = blockIdx.x*64;
    const int b  = blockIdx.y;
    const int tid = threadIdx.x, warp = tid>>5, lane = tid&31;
    const int r0 = warp*4;
    const int sbase = t0 - DEPTH_;
    const int jmin = (t0 < DEPTH_) ? DEPTH_ - t0 : 0;
    const float* qT = g_qkT + (size_t)b*128*T_;
    const unsigned qp_u = smem_u32(Qp);

    // Q via cp.async (once)
    #pragma unroll
    for (int i=0;i<2;i++){
        int u = tid + i*512, d = u>>4, c4 = u&15;
        cpa16(qp_u + (unsigned)(d*64 + c4*4)*4u, qT + (size_t)d*T_ + t0 + c4*4);
    }
    CPCOMMIT;

    // ---- QK: 32-col chunks, single smem buffer + register prefetch ----
    const int chs = jmin >> 5;
    const int kd = tid>>3, kc4 = (tid&7)*4;
    float4 kreg = *(const float4*)&qT[(size_t)(64+kd)*T_ + sbase + chs*32 + kc4];
    CPWAIT0;

    for (int ch = chs; ch < 10; ch++) {
        __syncthreads();                               // prev chunk reads done (+Q landed)
        *(float4*)&Kt[kd*32 + kc4] = kreg;
        if (ch + 1 < 10)
            kreg = *(const float4*)&qT[(size_t)(64+kd)*T_ + sbase + (ch+1)*32 + kc4];
        __syncthreads();                               // Kt ready
        u64t a0 = 0ull, a1 = 0ull;
        #pragma unroll 8
        for (int d = 0; d < 64; d++) {
            float4 qf = *(const float4*)&Qp[d*64 + r0]; // warp-uniform bcast
            ulonglong2 qq = *(ulonglong2*)&qf;
            u64t kk = dup2(Kt[d*32 + lane]);
            fma2(a0, qq.x, kk); fma2(a1, qq.y, kk);
        }
        float f0,f1,f2,f3; unpk(a0,f0,f1); unpk(a1,f2,f3);
        int c = ch*32 + lane;
        Ss[(r0+0)*SSTR+c]=f0; Ss[(r0+1)*SSTR+c]=f1;
        Ss[(r0+2)*SSTR+c]=f2; Ss[(r0+3)*SSTR+c]=f3;
    }
    __syncthreads();                 // all scores written; Qp/Kt free

    // prefetch first V chunk to regs (hidden under softmax)
    const int ch16 = jmin >> 4;
    const int vrow = tid>>6, vc4 = (tid&63)*4;
    float4 vr0 = *(const float4*)&g_qkv[((size_t)b*T_ + sbase + ch16*16 + vrow)*OCH + 128 + vc4];
    float4 vr1 = *(const float4*)&g_qkv[((size_t)b*T_ + sbase + ch16*16 + vrow + 8)*OCH + 128 + vc4];

    // ---- softmax: P = exp(s-max)/denom inside window, 0 outside ----
    {
        int r = tid>>3, g = tid&7, t = t0 + r;
        int jlo = (r+1 > jmin) ? r+1 : jmin;
        int jhi = r + DEPTH_;
        float mx = 0.f;
        for (int j = jlo + g; j <= jhi; j += 8)
            mx = fmaxf(mx, Ss[r*SSTR + j]);
        mx = fmaxf(mx, __shfl_xor_sync(0xffffffffu, mx, 1));
        mx = fmaxf(mx, __shfl_xor_sync(0xffffffffu, mx, 2));
        mx = fmaxf(mx, __shfl_xor_sync(0xffffffffu, mx, 4));
        float invd = 1.f / g_denom[t];
        for (int j = g; j < 320; j += 8) {
            float v = Ss[r*SSTR + j];
            Ss[r*SSTR + j] = (j >= jlo && j <= jhi) ? __expf(v - mx)*invd : 0.f;
        }
    }

    // ---- P @ V: warp = 8 rows x 128 cols; 16-row chunks, reg prefetch ----
    const int rg = warp >> 1, cg = warp & 1;
    const int r0p = rg * 8;
    const int cL = cg*128 + lane*4;
    const int jAw0 = (r0p+1 > jmin) ? r0p+1 : jmin;
    const int jAw = jAw0 & ~1;                       // even; extra j has P=0
    const int jBw = r0p + 7 + DEPTH_;                // <= 319
    u64t acc[8][2];
    #pragma unroll
    for (int i=0;i<8;i++){ acc[i][0]=0ull; acc[i][1]=0ull; }

    for (int ch = ch16; ch < 20; ch++) {
        __syncthreads();                             // softmax / prev reads done
        *(float4*)&Vs[vrow*256 + vc4]       = vr0;
        *(float4*)&Vs[(vrow+8)*256 + vc4]   = vr1;
        if (ch + 1 < 20) {
            vr0 = *(const float4*)&g_qkv[((size_t)b*T_ + sbase + (ch+1)*16 + vrow)*OCH + 128 + vc4];
            vr1 = *(const float4*)&g_qkv[((size_t)b*T_ + sbase + (ch+1)*16 + vrow + 8)*OCH + 128 + vc4];
        }
        __syncthreads();                             // Vs ready
        int c0 = ch*16;
        int bs = (c0 > jAw) ? c0 : jAw;              // even
        int be = (c0+14 < jBw) ? c0+14 : jBw;
        for (int j2 = bs; j2 <= be; j2 += 2) {
            int lr = j2 - c0;
            float4 v0 = *(const float4*)&Vs[lr*256 + cL];
            float4 v1 = *(const float4*)&Vs[(lr+1)*256 + cL];
            ulonglong2 vp0 = *(ulonglong2*)&v0, vp1 = *(ulonglong2*)&v1;
            #pragma unroll
            for (int i = 0; i < 8; i += 2) {
                float2 pa = *(const float2*)&Ss[(r0p+i)*SSTR + j2];     // uniform, 8B aligned
                float2 pb = *(const float2*)&Ss[(r0p+i+1)*SSTR + j2];   // uniform, 8B aligned
                u64t da = dup2(pa.x), db = dup2(pb.x);
                fma2(acc[i][0],   da, vp0.x); fma2(acc[i][1],   da, vp0.y);
                fma2(acc[i+1][0], db, vp0.x); fma2(acc[i+1][1], db, vp0.y);
                da = dup2(pa.y); db = dup2(pb.y);
                fma2(acc[i][0],   da, vp1.x); fma2(acc[i][1],   da, vp1.y);
                fma2(acc[i+1][0], db, vp1.x); fma2(acc[i+1][1], db, vp1.y);
            }
        }
    }

    // ---- epilogue: 8 consecutive t per col -> 2x float4 per col ----
    float o_[8][4];
    #pragma unroll
    for (int i=0;i<8;i++){
        unpk(acc[i][0], o_[i][0], o_[i][1]);
        unpk(acc[i][1], o_[i][2], o_[i][3]);
    }
    #pragma unroll
    for (int k=0;k<4;k++){
        size_t gi = ((size_t)b*C_ + cL + k)*T_ + t0 + r0p;
        float4 xa = *(const float4*)&x[gi];
        float4 o4 = make_float4(xa.x + o_[0][k], xa.y + o_[1][k],
                                xa.z + o_[2][k], xa.w + o_[3][k]);
        *(float4*)&y[gi] = o4;
        float4 xb = *(const float4*)&x[gi + 4];
        float4 o5 = make_float4(xb.x + o_[4][k], xb.y + o_[5][k],
                                xb.z + o_[6][k], xb.w + o_[7][k]);
        *(float4*)&y[gi + 4] = o5;
    }
}

// ---------------------------------------------------------------------------
extern "C" void kernel_launch(void* const* d_in, const int* in_sizes, int n_in,
                              void* d_out, int out_size)
{
    const float* x   = (const float*)d_in[0];
    const float* kW  = (const float*)d_in[1];
    const float* kb  = (const float*)d_in[2];
    const float* kg  = (const float*)d_in[3];
    const float* kbe = (const float*)d_in[4];
    const float* kmu = (const float*)d_in[5];
    const float* kva = (const float*)d_in[6];
    const float* qW  = (const float*)d_in[7];
    const float* qb  = (const float*)d_in[8];
    const float* qg  = (const float*)d_in[9];
    const float* qbe = (const float*)d_in[10];
    const float* qmu = (const float*)d_in[11];
    const float* qva = (const float*)d_in[12];
    const float* vW  = (const float*)d_in[13];
    const float* vb  = (const float*)d_in[14];
    const float* vg  = (const float*)d_in[15];
    const float* vbe = (const float*)d_in[16];
    const float* vmu = (const float*)d_in[17];
    const float* vva = (const float*)d_in[18];
    float* y = (float*)d_out;

    const int smem_attn = SM_F * sizeof(float);      // 107008 B -> 2 CTA/SM
    cudaFuncSetAttribute(attn_k, cudaFuncAttributeMaxDynamicSharedMemorySize, smem_attn);

    fold_k<<<C_, OCH>>>(kW,kb,kg,kbe,kmu,kva, qW,qb,qg,qbe,qmu,qva, vW,vb,vg,vbe,vmu,vva);
    proj_k<<<dim3(T_/128, OCH/64, B_), 256>>>(x);
    trans_k<<<dim3(T_/32, 4, B_), 256>>>();
    denom_k<<<T_/32, 256>>>();
    attn_k<<<dim3(T_/64, B_), 512, smem_attn>>>(x, y);
}